// round 5
// baseline (speedup 1.0000x reference)
#include <cuda_runtime.h>

#define SDIM 1024
#define DDIM 64
#define BH   16
#define NF   4

// Scratch: dp scores and attention probabilities (64 MB each).
__device__ float g_dp[(size_t)BH * SDIM * SDIM];
__device__ float g_attn[(size_t)BH * SDIM * SDIM];

// ---------------------------------------------------------------------------
// K1: dp[bh][s][t] = (1/8) * sum_d Q[bh][s][d] * K[bh][t][d]
// 64x64 tile per block, full K=64 resident in shared.
// ---------------------------------------------------------------------------
__global__ __launch_bounds__(256) void qk_kernel(const float* __restrict__ Q,
                                                 const float* __restrict__ Km) {
    __shared__ float As[64][68];  // [s][d], pre-scaled by 1/8
    __shared__ float Bs[64][68];  // [d][t]  (transposed so inner reads are contiguous)
    const int tid = threadIdx.x;
    const int bh = blockIdx.z;
    const int s0 = blockIdx.y * 64, t0 = blockIdx.x * 64;
    const float* Qh = Q  + (size_t)bh * SDIM * DDIM;
    const float* Kh = Km + (size_t)bh * SDIM * DDIM;

    // Load A tile (scaled)
    for (int i = tid; i < 64 * 16; i += 256) {
        int r = i >> 4, c4 = i & 15;
        float4 q = __ldg((const float4*)(Qh + (size_t)(s0 + r) * DDIM) + c4);
        q.x *= 0.125f; q.y *= 0.125f; q.z *= 0.125f; q.w *= 0.125f;
        *(float4*)&As[r][c4 * 4] = q;
    }
    // Load B tile transposed: Bs[d][t]
    for (int i = tid; i < 64 * 16; i += 256) {
        int r = i >> 4, c4 = i & 15;  // r = t, c4*4 = d base
        float4 kv = __ldg((const float4*)(Kh + (size_t)(t0 + r) * DDIM) + c4);
        int d = c4 * 4;
        Bs[d + 0][r] = kv.x; Bs[d + 1][r] = kv.y;
        Bs[d + 2][r] = kv.z; Bs[d + 3][r] = kv.w;
    }
    __syncthreads();

    const int tx = tid & 15, ty = tid >> 4;
    const int r0 = ty * 4, c0 = tx * 4;
    float acc[4][4] = {};
#pragma unroll
    for (int k = 0; k < 64; k++) {
        float4 b = *(const float4*)&Bs[k][c0];
        float a0 = As[r0 + 0][k];
        float a1 = As[r0 + 1][k];
        float a2 = As[r0 + 2][k];
        float a3 = As[r0 + 3][k];
        acc[0][0] += a0 * b.x; acc[0][1] += a0 * b.y; acc[0][2] += a0 * b.z; acc[0][3] += a0 * b.w;
        acc[1][0] += a1 * b.x; acc[1][1] += a1 * b.y; acc[1][2] += a1 * b.z; acc[1][3] += a1 * b.w;
        acc[2][0] += a2 * b.x; acc[2][1] += a2 * b.y; acc[2][2] += a2 * b.z; acc[2][3] += a2 * b.w;
        acc[3][0] += a3 * b.x; acc[3][1] += a3 * b.y; acc[3][2] += a3 * b.z; acc[3][3] += a3 * b.w;
    }

    float* out = g_dp + ((size_t)bh << 20);
#pragma unroll
    for (int i = 0; i < 4; i++) {
        float4 v = make_float4(acc[i][0], acc[i][1], acc[i][2], acc[i][3]);
        *(float4*)&out[(size_t)(s0 + r0 + i) * SDIM + t0 + c0] = v;
    }
}

// ---------------------------------------------------------------------------
// K2: fused conv(3x3,NF)+bias+leaky+linear+mask+softmax per row.
// One block per (bh, s). Reads 3 rows of g_dp, writes 1 row of g_attn.
// ---------------------------------------------------------------------------
__global__ __launch_bounds__(256) void conv_softmax_kernel(
    const int* __restrict__ mask,
    const float* __restrict__ cw, const float* __restrict__ cb,
    const float* __restrict__ lw, const float* __restrict__ lb) {
    __shared__ float rows[3][SDIM];
    __shared__ float red[9];
    const int tid = threadIdx.x;
    const int s = blockIdx.x, bh = blockIdx.y;
    const float* dpb = g_dp + ((size_t)bh << 20);

    // Load 3 neighboring dp rows (zero-pad vertically)
#pragma unroll
    for (int dr = 0; dr < 3; dr++) {
        int sr = s + dr - 1;
        if (sr >= 0 && sr < SDIM) {
            const float4* src = (const float4*)(dpb + (size_t)sr * SDIM);
            ((float4*)rows[dr])[tid] = __ldg(src + tid);
        } else {
            ((float4*)rows[dr])[tid] = make_float4(0.f, 0.f, 0.f, 0.f);
        }
    }

    // Weights in registers
    float w[NF][9], b_[NF], l_[NF];
#pragma unroll
    for (int f = 0; f < NF; f++) {
#pragma unroll
        for (int j = 0; j < 9; j++) w[f][j] = __ldg(&cw[f * 9 + j]);
        b_[f] = __ldg(&cb[f]);
        l_[f] = __ldg(&lw[f]);
    }
    const float lb0 = __ldg(lb);
    __syncthreads();

    const int bb = bh >> 3;  // batch index (H=8)
    const int* mrow = mask + ((size_t)bb * SDIM + s) * SDIM;

    float x[4];
#pragma unroll
    for (int q = 0; q < 4; q++) {
        int t = tid + q * 256;
        float v[9];
#pragma unroll
        for (int di = 0; di < 3; di++) {
#pragma unroll
            for (int dj = 0; dj < 3; dj++) {
                int tt = t + dj - 1;
                v[di * 3 + dj] = (tt >= 0 && tt < SDIM) ? rows[di][tt] : 0.f;
            }
        }
        float pre = lb0;
#pragma unroll
        for (int f = 0; f < NF; f++) {
            float c = b_[f];
#pragma unroll
            for (int j = 0; j < 9; j++) c += w[f][j] * v[j];
            // leaky_relu(c, 0.01) == fmaxf(c, 0.01*c)
            pre += l_[f] * fmaxf(c, 0.01f * c);
        }
        if (__ldg(&mrow[t]) == 0) pre = -1e30f;
        x[q] = pre;
    }

    // --- block softmax over 1024 elements ---
    float m = fmaxf(fmaxf(x[0], x[1]), fmaxf(x[2], x[3]));
#pragma unroll
    for (int off = 16; off; off >>= 1)
        m = fmaxf(m, __shfl_xor_sync(0xffffffffu, m, off));
    if ((tid & 31) == 0) red[tid >> 5] = m;
    __syncthreads();
    if (tid == 0) {
        float mm = red[0];
#pragma unroll
        for (int i = 1; i < 8; i++) mm = fmaxf(mm, red[i]);
        red[8] = mm;
    }
    __syncthreads();
    m = red[8];

    float e[4];
    float ssum = 0.f;
#pragma unroll
    for (int q = 0; q < 4; q++) { e[q] = __expf(x[q] - m); ssum += e[q]; }
#pragma unroll
    for (int off = 16; off; off >>= 1)
        ssum += __shfl_xor_sync(0xffffffffu, ssum, off);
    if ((tid & 31) == 0) red[tid >> 5] = ssum;
    __syncthreads();
    if (tid == 0) {
        float sm = red[0];
#pragma unroll
        for (int i = 1; i < 8; i++) sm += red[i];
        red[8] = sm;
    }
    __syncthreads();
    const float inv = 1.0f / red[8];

    float* arow = g_attn + ((size_t)bh << 20) + (size_t)s * SDIM;
#pragma unroll
    for (int q = 0; q < 4; q++) arow[tid + q * 256] = e[q] * inv;
}

// ---------------------------------------------------------------------------
// K3: out[bh][s][d] = sum_t attn[bh][s][t] * V[bh][t][d]
// 64-row x 64-col tile per block, K chunked by 16.
// ---------------------------------------------------------------------------
__global__ __launch_bounds__(256) void av_kernel(const float* __restrict__ V,
                                                 float* __restrict__ out) {
    __shared__ float As[64][20];  // attn tile: [s][t-chunk], stride 20 (80B, 16B-aligned)
    __shared__ float Bs[16][68];  // V tile:    [t][d],       stride 68 (272B, 16B-aligned)
    const int tid = threadIdx.x;
    const int bh = blockIdx.y;
    const int s0 = blockIdx.x * 64;
    const float* attn = g_attn + ((size_t)bh << 20);
    const float* Vh = V + (size_t)bh * SDIM * DDIM;
    const int tx = tid & 15, ty = tid >> 4;
    const int r0 = ty * 4, c0 = tx * 4;

    float acc[4][4] = {};
    for (int k0 = 0; k0 < SDIM; k0 += 16) {
        {   // load attn tile 64x16
            int r = tid >> 2, c4 = tid & 3;
            float4 a = __ldg((const float4*)(attn + (size_t)(s0 + r) * SDIM + k0) + c4);
            *(float4*)&As[r][c4 * 4] = a;
        }
        {   // load V tile 16x64
            int r = tid >> 4, c4 = tid & 15;
            float4 b = __ldg((const float4*)(Vh + (size_t)(k0 + r) * DDIM) + c4);
            *(float4*)&Bs[r][c4 * 4] = b;
        }
        __syncthreads();
#pragma unroll
        for (int k = 0; k < 16; k++) {
            float4 b = *(const float4*)&Bs[k][c0];
            float a0 = As[r0 + 0][k];
            float a1 = As[r0 + 1][k];
            float a2 = As[r0 + 2][k];
            float a3 = As[r0 + 3][k];
            acc[0][0] += a0 * b.x; acc[0][1] += a0 * b.y; acc[0][2] += a0 * b.z; acc[0][3] += a0 * b.w;
            acc[1][0] += a1 * b.x; acc[1][1] += a1 * b.y; acc[1][2] += a1 * b.z; acc[1][3] += a1 * b.w;
            acc[2][0] += a2 * b.x; acc[2][1] += a2 * b.y; acc[2][2] += a2 * b.z; acc[2][3] += a2 * b.w;
            acc[3][0] += a3 * b.x; acc[3][1] += a3 * b.y; acc[3][2] += a3 * b.z; acc[3][3] += a3 * b.w;
        }
        __syncthreads();
    }

#pragma unroll
    for (int i = 0; i < 4; i++) {
        float4 v = make_float4(acc[i][0], acc[i][1], acc[i][2], acc[i][3]);
        *(float4*)&out[((size_t)bh * SDIM + s0 + r0 + i) * DDIM + c0] = v;
    }
}

extern "C" void kernel_launch(void* const* d_in, const int* in_sizes, int n_in,
                              void* d_out, int out_size) {
    const float* Q    = (const float*)d_in[0];
    const float* Kp   = (const float*)d_in[1];
    const float* V    = (const float*)d_in[2];
    const int*   mask = (const int*)d_in[3];
    const float* cw   = (const float*)d_in[4];
    const float* cb   = (const float*)d_in[5];
    const float* lw   = (const float*)d_in[6];
    const float* lb   = (const float*)d_in[7];
    float* out = (float*)d_out;

    dim3 g1(SDIM / 64, SDIM / 64, BH);
    qk_kernel<<<g1, 256>>>(Q, Kp);

    dim3 g2(SDIM, BH);
    conv_softmax_kernel<<<g2, 256>>>(mask, cw, cb, lw, lb);

    dim3 g3(SDIM / 64, BH);
    av_kernel<<<g3, 256>>>(V, out);
}

// round 9
// speedup vs baseline: 1.1435x; 1.1435x over previous
#include <cuda_runtime.h>

#define SDIM 1024
#define DDIM 64
#define BH   16
#define NF   4
#define R2   4   // rows per conv/softmax block

// Scratch: dp scores and attention probabilities (64 MB each).
__device__ float g_dp[(size_t)BH * SDIM * SDIM];
__device__ float g_attn[(size_t)BH * SDIM * SDIM];

// ---------------------------------------------------------------------------
// K1: dp[bh][s][t] = (1/8) * sum_d Q[bh][s][d] * K[bh][t][d]
// 64x64 tile per block, full K=64 resident in shared. (~87% of fp32 FFMA floor)
// ---------------------------------------------------------------------------
__global__ __launch_bounds__(256) void qk_kernel(const float* __restrict__ Q,
                                                 const float* __restrict__ Km) {
    __shared__ float As[64][68];  // [s][d], pre-scaled by 1/8
    __shared__ float Bs[64][68];  // [d][t]
    const int tid = threadIdx.x;
    const int bh = blockIdx.z;
    const int s0 = blockIdx.y * 64, t0 = blockIdx.x * 64;
    const float* Qh = Q  + (size_t)bh * SDIM * DDIM;
    const float* Kh = Km + (size_t)bh * SDIM * DDIM;

    for (int i = tid; i < 64 * 16; i += 256) {
        int r = i >> 4, c4 = i & 15;
        float4 q = __ldg((const float4*)(Qh + (size_t)(s0 + r) * DDIM) + c4);
        q.x *= 0.125f; q.y *= 0.125f; q.z *= 0.125f; q.w *= 0.125f;
        *(float4*)&As[r][c4 * 4] = q;
    }
    for (int i = tid; i < 64 * 16; i += 256) {
        int r = i >> 4, c4 = i & 15;
        float4 kv = __ldg((const float4*)(Kh + (size_t)(t0 + r) * DDIM) + c4);
        int d = c4 * 4;
        Bs[d + 0][r] = kv.x; Bs[d + 1][r] = kv.y;
        Bs[d + 2][r] = kv.z; Bs[d + 3][r] = kv.w;
    }
    __syncthreads();

    const int tx = tid & 15, ty = tid >> 4;
    const int r0 = ty * 4, c0 = tx * 4;
    float acc[4][4] = {};
#pragma unroll
    for (int k = 0; k < 64; k++) {
        float4 b = *(const float4*)&Bs[k][c0];
        float a0 = As[r0 + 0][k];
        float a1 = As[r0 + 1][k];
        float a2 = As[r0 + 2][k];
        float a3 = As[r0 + 3][k];
        acc[0][0] += a0 * b.x; acc[0][1] += a0 * b.y; acc[0][2] += a0 * b.z; acc[0][3] += a0 * b.w;
        acc[1][0] += a1 * b.x; acc[1][1] += a1 * b.y; acc[1][2] += a1 * b.z; acc[1][3] += a1 * b.w;
        acc[2][0] += a2 * b.x; acc[2][1] += a2 * b.y; acc[2][2] += a2 * b.z; acc[2][3] += a2 * b.w;
        acc[3][0] += a3 * b.x; acc[3][1] += a3 * b.y; acc[3][2] += a3 * b.z; acc[3][3] += a3 * b.w;
    }

    float* out = g_dp + ((size_t)bh << 20);
#pragma unroll
    for (int i = 0; i < 4; i++) {
        float4 v = make_float4(acc[i][0], acc[i][1], acc[i][2], acc[i][3]);
        *(float4*)&out[(size_t)(s0 + r0 + i) * SDIM + t0 + c0] = v;
    }
}

// ---------------------------------------------------------------------------
// K2: fused conv(3x3,NF)+bias+leaky+linear+mask+softmax.
// R2=4 output rows per block sharing a 6-row dp window (1.5x reads vs 3x).
// ---------------------------------------------------------------------------
__global__ __launch_bounds__(256) void conv_softmax_kernel(
    const int* __restrict__ mask,
    const float* __restrict__ cw, const float* __restrict__ cb,
    const float* __restrict__ lw, const float* __restrict__ lb) {
    __shared__ float rows[R2 + 2][SDIM];  // 24 KB
    __shared__ float red[9];
    const int tid = threadIdx.x;
    const int s0 = blockIdx.x * R2, bh = blockIdx.y;
    const float* dpb = g_dp + ((size_t)bh << 20);

    // Load R2+2 dp rows (zero-pad vertically)
#pragma unroll
    for (int j = 0; j < R2 + 2; j++) {
        int sr = s0 + j - 1;
        if (sr >= 0 && sr < SDIM) {
            const float4* src = (const float4*)(dpb + (size_t)sr * SDIM);
            ((float4*)rows[j])[tid] = __ldg(src + tid);
        } else {
            ((float4*)rows[j])[tid] = make_float4(0.f, 0.f, 0.f, 0.f);
        }
    }

    float w[NF][9], b_[NF], l_[NF];
#pragma unroll
    for (int f = 0; f < NF; f++) {
#pragma unroll
        for (int j = 0; j < 9; j++) w[f][j] = __ldg(&cw[f * 9 + j]);
        b_[f] = __ldg(&cb[f]);
        l_[f] = __ldg(&lw[f]);
    }
    const float lb0 = __ldg(lb);
    const int bb = bh >> 3;  // batch (H=8)
    __syncthreads();

    for (int r = 0; r < R2; r++) {
        const int s = s0 + r;
        const int* mrow = mask + ((size_t)bb * SDIM + s) * SDIM;

        float x[4];
#pragma unroll
        for (int q = 0; q < 4; q++) {
            int t = tid + q * 256;
            float v[9];
#pragma unroll
            for (int di = 0; di < 3; di++) {
#pragma unroll
                for (int dj = 0; dj < 3; dj++) {
                    int tt = t + dj - 1;
                    v[di * 3 + dj] = (tt >= 0 && tt < SDIM) ? rows[r + di][tt] : 0.f;
                }
            }
            float pre = lb0;
#pragma unroll
            for (int f = 0; f < NF; f++) {
                float c = b_[f];
#pragma unroll
                for (int j = 0; j < 9; j++) c += w[f][j] * v[j];
                pre += l_[f] * fmaxf(c, 0.01f * c);  // leaky_relu
            }
            if (__ldg(&mrow[t]) == 0) pre = -1e30f;
            x[q] = pre;
        }

        // block softmax over 1024
        float m = fmaxf(fmaxf(x[0], x[1]), fmaxf(x[2], x[3]));
#pragma unroll
        for (int off = 16; off; off >>= 1)
            m = fmaxf(m, __shfl_xor_sync(0xffffffffu, m, off));
        if ((tid & 31) == 0) red[tid >> 5] = m;
        __syncthreads();
        if (tid == 0) {
            float mm = red[0];
#pragma unroll
            for (int i = 1; i < 8; i++) mm = fmaxf(mm, red[i]);
            red[8] = mm;
        }
        __syncthreads();
        m = red[8];
        __syncthreads();  // everyone read red[8] before reuse

        float e[4], ssum = 0.f;
#pragma unroll
        for (int q = 0; q < 4; q++) { e[q] = __expf(x[q] - m); ssum += e[q]; }
#pragma unroll
        for (int off = 16; off; off >>= 1)
            ssum += __shfl_xor_sync(0xffffffffu, ssum, off);
        if ((tid & 31) == 0) red[tid >> 5] = ssum;
        __syncthreads();
        if (tid == 0) {
            float sm = red[0];
#pragma unroll
            for (int i = 1; i < 8; i++) sm += red[i];
            red[8] = sm;
        }
        __syncthreads();
        const float inv = 1.0f / red[8];
        __syncthreads();  // everyone read red[8] before next-iter reuse

        float* arow = g_attn + ((size_t)bh << 20) + (size_t)s * SDIM;
#pragma unroll
        for (int q = 0; q < 4; q++) arow[tid + q * 256] = e[q] * inv;
    }
}

// ---------------------------------------------------------------------------
// K3: out[bh][s][d] = sum_t attn[bh][s][t] * V[bh][t][d]
// 64(s) x 64(d) tile, K chunked by 64 (4x fewer barriers than KC=16),
// same inner-loop structure as K1.
// ---------------------------------------------------------------------------
__global__ __launch_bounds__(256) void av_kernel(const float* __restrict__ V,
                                                 float* __restrict__ out) {
    __shared__ float As[64][68];  // attn tile [s][k]
    __shared__ float Bs[64][68];  // V tile    [k][d]
    const int tid = threadIdx.x;
    const int bh = blockIdx.y;
    const int s0 = blockIdx.x * 64;
    const float* attn = g_attn + ((size_t)bh << 20);
    const float* Vh = V + (size_t)bh * SDIM * DDIM;
    const int tx = tid & 15, ty = tid >> 4;
    const int r0 = ty * 4, c0 = tx * 4;

    float acc[4][4] = {};
    for (int k0 = 0; k0 < SDIM; k0 += 64) {
#pragma unroll
        for (int j = 0; j < 4; j++) {   // attn tile 64x64
            int i = tid + j * 256;
            int r = i >> 4, c4 = i & 15;
            float4 a = __ldg((const float4*)(attn + (size_t)(s0 + r) * SDIM + k0) + c4);
            *(float4*)&As[r][c4 * 4] = a;
        }
#pragma unroll
        for (int j = 0; j < 4; j++) {   // V tile 64x64
            int i = tid + j * 256;
            int r = i >> 4, c4 = i & 15;
            float4 b = __ldg((const float4*)(Vh + (size_t)(k0 + r) * DDIM) + c4);
            *(float4*)&Bs[r][c4 * 4] = b;
        }
        __syncthreads();
#pragma unroll 16
        for (int k = 0; k < 64; k++) {
            float4 b = *(const float4*)&Bs[k][c0];
            float a0 = As[r0 + 0][k];
            float a1 = As[r0 + 1][k];
            float a2 = As[r0 + 2][k];
            float a3 = As[r0 + 3][k];
            acc[0][0] += a0 * b.x; acc[0][1] += a0 * b.y; acc[0][2] += a0 * b.z; acc[0][3] += a0 * b.w;
            acc[1][0] += a1 * b.x; acc[1][1] += a1 * b.y; acc[1][2] += a1 * b.z; acc[1][3] += a1 * b.w;
            acc[2][0] += a2 * b.x; acc[2][1] += a2 * b.y; acc[2][2] += a2 * b.z; acc[2][3] += a2 * b.w;
            acc[3][0] += a3 * b.x; acc[3][1] += a3 * b.y; acc[3][2] += a3 * b.z; acc[3][3] += a3 * b.w;
        }
        __syncthreads();
    }

#pragma unroll
    for (int i = 0; i < 4; i++) {
        float4 v = make_float4(acc[i][0], acc[i][1], acc[i][2], acc[i][3]);
        *(float4*)&out[((size_t)bh * SDIM + s0 + r0 + i) * DDIM + c0] = v;
    }
}

extern "C" void kernel_launch(void* const* d_in, const int* in_sizes, int n_in,
                              void* d_out, int out_size) {
    const float* Q    = (const float*)d_in[0];
    const float* Kp   = (const float*)d_in[1];
    const float* V    = (const float*)d_in[2];
    const int*   mask = (const int*)d_in[3];
    const float* cw   = (const float*)d_in[4];
    const float* cb   = (const float*)d_in[5];
    const float* lw   = (const float*)d_in[6];
    const float* lb   = (const float*)d_in[7];
    float* out = (float*)d_out;

    dim3 g1(SDIM / 64, SDIM / 64, BH);
    qk_kernel<<<g1, 256>>>(Q, Kp);

    dim3 g2(SDIM / R2, BH);
    conv_softmax_kernel<<<g2, 256>>>(mask, cw, cb, lw, lb);

    dim3 g3(SDIM / 64, BH);
    av_kernel<<<g3, 256>>>(V, out);
}